// round 1
// baseline (speedup 1.0000x reference)
#include <cuda_runtime.h>
#include <cuda_bf16.h>

// Problem geometry: [B=4, 1, D=160, H=160, W=160]
#define NB 4
#define S  160
#define PLANE      (S * S)          // 25600 elems per (b,d) plane
#define PLANE4     (PLANE / 4)      // 6400 int4/float4 per plane
#define NPLANES    (NB * S)         // 640
#define TOTAL_ELEMS (4.0 * 160.0 * 160.0 * 160.0)

// ---- device scratch (no allocations allowed) ----
__device__ unsigned char g_any[NB][3][S];  // axis projections: 0=D,1=H,2=W
__device__ int    g_lo[NB][3];
__device__ int    g_hi[NB][3];
__device__ int    g_fg[NB];
__device__ double g_acc;

// ---------------- kernel 0: zero scratch (every replay) ----------------
__global__ void k_init() {
    int t = blockIdx.x * blockDim.x + threadIdx.x;
    if (t == 0) g_acc = 0.0;
    if (t < NB * 3 * S) ((unsigned char*)g_any)[t] = 0;
}

// ---------------- kernel 1: mask -> axis projections ----------------
// One block per (b,d) plane. int4 loads; shared flag arrays; benign-race
// plain stores of 1 into tiny global arrays (all writers write 1).
__global__ __launch_bounds__(256) void k_proj(const int* __restrict__ mask) {
    __shared__ unsigned char sH[S];
    __shared__ unsigned char sW[S];
    __shared__ int sD;

    const int bx = blockIdx.x;          // 0..639
    const int b  = bx / S;
    const int d  = bx - b * S;
    const int tid = threadIdx.x;

    if (tid < S) { sH[tid] = 0; sW[tid] = 0; }
    if (tid == 0) sD = 0;
    __syncthreads();

    const int4* M = (const int4*)mask + (size_t)bx * PLANE4;

    int planeAny = 0;
    for (int i = tid; i < PLANE4; i += 256) {
        int4 v = M[i];
        int any4 = v.x | v.y | v.z | v.w;
        if (any4) {
            planeAny = 1;
            int h  = i / 40;            // 40 int4 per W-row
            int w0 = (i - h * 40) * 4;
            sH[h] = 1;
            if (v.x) sW[w0 + 0] = 1;
            if (v.y) sW[w0 + 1] = 1;
            if (v.z) sW[w0 + 2] = 1;
            if (v.w) sW[w0 + 3] = 1;
        }
    }
    if (planeAny) sD = 1;
    __syncthreads();

    if (tid < S) {
        if (sH[tid]) g_any[b][1][tid] = 1;
        if (sW[tid]) g_any[b][2][tid] = 1;
    }
    if (tid == 0 && sD) g_any[b][0][d] = 1;
}

// ---------------- kernel 2: projections -> bbox (exact f32 reference math) --
__global__ void k_bbox() {
    int t = threadIdx.x;                 // one thread per (b, axis)
    if (t >= NB * 3) return;
    int b  = t / 3;
    int ax = t - b * 3;

    int mn = -1, mx = -1;
    for (int i = 0; i < S; i++) {
        if (g_any[b][ax][i]) { if (mn < 0) mn = i; mx = i; }
    }
    int fg = (mn >= 0);
    if (ax == 0) g_fg[b] = fg;

    int lo = 0, hi = 0;
    if (fg) {
        float mnf = (float)mn, mxf = (float)mx;
        float c = (mxf + mnf) * 0.5f;
        float e = (mxf - mnf + 1.0f) * 0.5f * 1.2f;   // EXPAND
        lo = (int)fmaxf(0.0f,  floorf(c - e));
        hi = (int)fminf((float)(S - 1), floorf(c + e)); // EXCLUSIVE bound
    }
    g_lo[b][ax] = lo;
    g_hi[b][ax] = hi;
}

// ---------------- kernel 3: weighted SSE reduction ----------------
// One block per (b,d) plane; float4 streaming; w^2 in {1, 0.01}.
__global__ __launch_bounds__(256) void k_main(const float* __restrict__ pred,
                                              const float* __restrict__ truth) {
    const int bx = blockIdx.x;
    const int b  = bx / S;
    const int d  = bx - b * S;
    const int tid = threadIdx.x;

    const int fg   = g_fg[b];
    const int loD  = g_lo[b][0], hiD = g_hi[b][0];
    const int loH  = g_lo[b][1], hiH = g_hi[b][1];
    const int loW  = g_lo[b][2], hiW = g_hi[b][2];
    const bool inD = fg && (d >= loD) && (d < hiD);

    const float4* P = (const float4*)pred  + (size_t)bx * PLANE4;
    const float4* T = (const float4*)truth + (size_t)bx * PLANE4;

    float acc = 0.0f;
    #pragma unroll 5
    for (int i = tid; i < PLANE4; i += 256) {
        float4 p = P[i];
        float4 t = T[i];
        int h  = i / 40;
        int w0 = (i - h * 40) * 4;
        bool inH = inD && (h >= loH) && (h < hiH);

        float wx = (inH && (w0 + 0) >= loW && (w0 + 0) < hiW) ? 1.0f : 0.01f;
        float wy = (inH && (w0 + 1) >= loW && (w0 + 1) < hiW) ? 1.0f : 0.01f;
        float wz = (inH && (w0 + 2) >= loW && (w0 + 2) < hiW) ? 1.0f : 0.01f;
        float ww = (inH && (w0 + 3) >= loW && (w0 + 3) < hiW) ? 1.0f : 0.01f;

        float dx = p.x - t.x, dy = p.y - t.y, dz = p.z - t.z, dw = p.w - t.w;
        acc += wx * dx * dx;
        acc += wy * dy * dy;
        acc += wz * dz * dz;
        acc += ww * dw * dw;
    }

    // warp reduce (float), then block reduce (double), one atomicAdd per block
    #pragma unroll
    for (int off = 16; off > 0; off >>= 1)
        acc += __shfl_xor_sync(0xFFFFFFFFu, acc, off);

    __shared__ double warpSum[8];
    int lane = tid & 31, wid = tid >> 5;
    if (lane == 0) warpSum[wid] = (double)acc;
    __syncthreads();
    if (tid == 0) {
        double s = 0.0;
        #pragma unroll
        for (int w = 0; w < 8; w++) s += warpSum[w];
        atomicAdd(&g_acc, s);
    }
}

// ---------------- kernel 4: finalize ----------------
__global__ void k_final(float* __restrict__ out) {
    out[0] = (float)(g_acc / TOTAL_ELEMS);
}

extern "C" void kernel_launch(void* const* d_in, const int* in_sizes, int n_in,
                              void* d_out, int out_size) {
    const float* y_pred = (const float*)d_in[0];
    const float* y_true = (const float*)d_in[1];
    const int*   mask   = (const int*)d_in[2];
    float* out = (float*)d_out;

    k_init<<<2, 1024>>>();
    k_proj<<<NPLANES, 256>>>(mask);
    k_bbox<<<1, 32>>>();
    k_main<<<NPLANES, 256>>>(y_pred, y_true);
    k_final<<<1, 1>>>(out);
}